// round 10
// baseline (speedup 1.0000x reference)
#include <cuda_runtime.h>
#include <cuda_bf16.h>
#include <math.h>
#include <stdint.h>

// AfmoeTokenChoiceRouter — 3x-bf16-split mma.sync GEMM + exact fp64 boundary refinement
// logits = x[T,H] @ W^T (T=16384, H=2048, E=64); sigmoid; biased top-8; norm; *2.5
// Output: [ top_scores (T*8 f32) | selected_experts as f32 (T*8) ]

#define TOKS   128
#define TPB    256
#define TOPK   8
#define ROUTE_SCALE 2.5f
#define TAU    5e-5f               // biased-score gap threshold for exact refinement

#define A_RS    40                 // A row stride in words (32 data + 8 pad)
#define A_LVL   (TOKS * A_RS)      // 5120 words per level
#define B_LVL   1024               // 2 ks * 64 n * 8 words
#define BUFW    (3*A_LVL + 3*B_LVL)  // 18432 words
#define B_OFF   (3*A_LVL)
#define DYN_BYTES (2 * BUFW * 4)   // 147456

// Pre-split W image: [kb(64)][lvl(3)][ks(2)][n(64)][pos(8)] bf16x2 words
__device__ uint32_t g_B[196608];

static __device__ __forceinline__ uint32_t pk2(__nv_bfloat16 a, __nv_bfloat16 b){
    return ((uint32_t)__bfloat16_as_ushort(b) << 16) | (uint32_t)__bfloat16_as_ushort(a);
}
static __device__ __forceinline__ void mma_bf16(float* c,
        uint32_t a0, uint32_t a1, uint32_t a2, uint32_t a3,
        uint32_t b0, uint32_t b1){
    asm volatile("mma.sync.aligned.m16n8k16.row.col.f32.bf16.bf16.f32 "
        "{%0,%1,%2,%3}, {%4,%5,%6,%7}, {%8,%9}, {%0,%1,%2,%3};"
        : "+f"(c[0]), "+f"(c[1]), "+f"(c[2]), "+f"(c[3])
        : "r"(a0), "r"(a1), "r"(a2), "r"(a3), "r"(b0), "r"(b1));
}

// ---------- prep: exact 3-level bf16 split of W, frag-permuted ----------
__global__ void prep_w_kernel(const float* __restrict__ w, int H){
    int half = H >> 1;
    int idx = blockIdx.x * blockDim.x + threadIdx.x;
    if (idx >= 64 * half) return;
    int e  = idx / half;
    int k  = (idx - e * half) * 2;
    float v0 = w[(size_t)e * H + k];
    float v1 = w[(size_t)e * H + k + 1];
    int kb = k >> 5, ks = (k >> 4) & 1, j = (k & 15) >> 1;
    int pos = (j < 4) ? 2 * j : 2 * (j - 4) + 1;
    size_t base = (size_t)kb * 3072 + (size_t)ks * 512 + (size_t)e * 8 + pos;
    #pragma unroll
    for (int L = 0; L < 3; L++){
        __nv_bfloat16 h0 = __float2bfloat16(v0);
        __nv_bfloat16 h1 = __float2bfloat16(v1);
        g_B[base + (size_t)L * 1024] = pk2(h0, h1);
        v0 -= __bfloat162float(h0);
        v1 -= __bfloat162float(h1);
    }
}

// ---------- main ----------
__global__ __launch_bounds__(TPB, 1)
void router_main(const float* __restrict__ x, const float* __restrict__ bias,
                 const float* __restrict__ w, float* __restrict__ out, int T, int H)
{
    extern __shared__ __align__(16) uint32_t dyn[];
    __shared__ float Sb[64];

    const int tid  = threadIdx.x;
    const int warp = tid >> 5;
    const int lane = tid & 31;
    const int wm   = warp & 3;
    const int wn   = warp >> 2;
    const int g    = lane >> 2;
    const int c    = lane & 3;
    const int tok0 = blockIdx.x * TOKS;
    const int nchunk = H >> 5;

    if (tid < 64) Sb[tid] = bias[tid];

    const int rrow = tid >> 2;
    const int sks  = (tid >> 1) & 1;
    const int sh   = tid & 1;
    const float* xp0 = x + (size_t)(tok0 + rrow)      * H + sks * 16 + sh * 4;
    const float* xp1 = x + (size_t)(tok0 + rrow + 64) * H + sks * 16 + sh * 4;

    float4 va[2][2];
    uint4  vb[3];
    const uint4* gB4 = (const uint4*)g_B;

    va[0][0] = *(const float4*)(xp0);  va[0][1] = *(const float4*)(xp0 + 8);
    va[1][0] = *(const float4*)(xp1);  va[1][1] = *(const float4*)(xp1 + 8);
    #pragma unroll
    for (int i = 0; i < 3; i++) vb[i] = gB4[tid + i * 256];

    float acc[2][4][4];
    #pragma unroll
    for (int mb = 0; mb < 2; mb++)
        #pragma unroll
        for (int nb = 0; nb < 4; nb++)
            #pragma unroll
            for (int q = 0; q < 4; q++) acc[mb][nb][q] = 0.0f;

    for (int kb = 0; kb < nchunk; kb++){
        uint32_t* Ab = dyn + (kb & 1) * BUFW;
        uint32_t* Bb = Ab + B_OFF;

        #pragma unroll
        for (int jr = 0; jr < 2; jr++){
            float e0 = va[jr][0].x, e1 = va[jr][0].y, e2 = va[jr][0].z, e3 = va[jr][0].w;
            float e4 = va[jr][1].x, e5 = va[jr][1].y, e6 = va[jr][1].z, e7 = va[jr][1].w;
            const int addr = (rrow + 64 * jr) * A_RS + sks * 16 + sh * 4;
            #pragma unroll
            for (int L = 0; L < 3; L++){
                __nv_bfloat16 h0 = __float2bfloat16(e0), h1 = __float2bfloat16(e1);
                __nv_bfloat16 h2 = __float2bfloat16(e2), h3 = __float2bfloat16(e3);
                __nv_bfloat16 h4 = __float2bfloat16(e4), h5 = __float2bfloat16(e5);
                __nv_bfloat16 h6 = __float2bfloat16(e6), h7 = __float2bfloat16(e7);
                uint4 s;
                s.x = pk2(h0, h1); s.y = pk2(h4, h5);
                s.z = pk2(h2, h3); s.w = pk2(h6, h7);
                *(uint4*)(Ab + L * A_LVL + addr) = s;
                if (L < 2){
                    e0 -= __bfloat162float(h0); e1 -= __bfloat162float(h1);
                    e2 -= __bfloat162float(h2); e3 -= __bfloat162float(h3);
                    e4 -= __bfloat162float(h4); e5 -= __bfloat162float(h5);
                    e6 -= __bfloat162float(h6); e7 -= __bfloat162float(h7);
                }
            }
        }
        #pragma unroll
        for (int i = 0; i < 3; i++) *(uint4*)(Bb + (tid + i * 256) * 4) = vb[i];
        __syncthreads();

        if (kb + 1 < nchunk){
            const float* p0 = xp0 + (size_t)(kb + 1) * 32;
            const float* p1 = xp1 + (size_t)(kb + 1) * 32;
            va[0][0] = *(const float4*)(p0);  va[0][1] = *(const float4*)(p0 + 8);
            va[1][0] = *(const float4*)(p1);  va[1][1] = *(const float4*)(p1 + 8);
            #pragma unroll
            for (int i = 0; i < 3; i++)
                vb[i] = gB4[(size_t)(kb + 1) * 768 + tid + i * 256];
        }

        #pragma unroll
        for (int ks = 0; ks < 2; ks++){
            uint2 bf[3][4];
            #pragma unroll
            for (int L = 0; L < 3; L++)
                #pragma unroll
                for (int nb = 0; nb < 4; nb++)
                    bf[L][nb] = *(const uint2*)(Bb + L * B_LVL + ks * 512
                                                + (wn * 32 + nb * 8 + g) * 8 + 2 * c);
            #pragma unroll
            for (int mb = 0; mb < 2; mb++){
                const int ab = (wm * 32 + mb * 16 + g) * A_RS + ks * 16 + 2 * c;
                uint2 A1  = *(const uint2*)(Ab + ab);
                uint2 A1b = *(const uint2*)(Ab + ab + 8 * A_RS);
                uint2 A2  = *(const uint2*)(Ab + A_LVL + ab);
                uint2 A2b = *(const uint2*)(Ab + A_LVL + ab + 8 * A_RS);
                uint2 A3  = *(const uint2*)(Ab + 2 * A_LVL + ab);
                uint2 A3b = *(const uint2*)(Ab + 2 * A_LVL + ab + 8 * A_RS);
                #pragma unroll
                for (int nb = 0; nb < 4; nb++){
                    float* a = acc[mb][nb];
                    mma_bf16(a, A1.x, A1b.x, A1.y, A1b.y, bf[0][nb].x, bf[0][nb].y);
                    mma_bf16(a, A1.x, A1b.x, A1.y, A1b.y, bf[1][nb].x, bf[1][nb].y);
                    mma_bf16(a, A2.x, A2b.x, A2.y, A2b.y, bf[0][nb].x, bf[0][nb].y);
                    mma_bf16(a, A1.x, A1b.x, A1.y, A1b.y, bf[2][nb].x, bf[2][nb].y);
                    mma_bf16(a, A2.x, A2b.x, A2.y, A2b.y, bf[1][nb].x, bf[1][nb].y);
                    mma_bf16(a, A3.x, A3b.x, A3.y, A3b.y, bf[0][nb].x, bf[0][nb].y);
                    mma_bf16(a, A2.x, A2b.x, A2.y, A2b.y, bf[2][nb].x, bf[2][nb].y);
                    mma_bf16(a, A3.x, A3b.x, A3.y, A3b.y, bf[1][nb].x, bf[1][nb].y);
                }
            }
        }
        __syncthreads();
    }

    // ---- epilogue: sigmoid -> SMEM score tile (stride 66) ----
    float* Sc = (float*)dyn;
    {
        const int r0 = wm * 32 + g;
        const int c0 = wn * 32 + 2 * c;
        #pragma unroll
        for (int mb = 0; mb < 2; mb++)
            #pragma unroll
            for (int nb = 0; nb < 4; nb++){
                int r = r0 + mb * 16;
                int cc = c0 + nb * 8;
                Sc[r * 66 + cc]           = 1.0f / (1.0f + expf(-acc[mb][nb][0]));
                Sc[r * 66 + cc + 1]       = 1.0f / (1.0f + expf(-acc[mb][nb][1]));
                Sc[(r + 8) * 66 + cc]     = 1.0f / (1.0f + expf(-acc[mb][nb][2]));
                Sc[(r + 8) * 66 + cc + 1] = 1.0f / (1.0f + expf(-acc[mb][nb][3]));
            }
    }
    __syncthreads();

    // ---- top-10 selection + exact refinement for boundary-risk tokens ----
    const unsigned FULL = 0xFFFFFFFFu;
    for (int t = 0; t < 16; t++){
        const int tl = warp * 16 + t;
        const int gt = tok0 + tl;
        const int e0 = lane, e1 = lane + 32;
        float b0v = Sc[tl * 66 + e0] + Sb[e0];
        float b1v = Sc[tl * 66 + e1] + Sb[e1];

        float myval = 0.0f, mybv = -1e30f;
        int   myidx = 0;
        float ssum  = 0.0f;

        #pragma unroll
        for (int i = 0; i < 10; i++){
            float v; int idx;
            if (b0v >= b1v) { v = b0v; idx = e0; }
            else            { v = b1v; idx = e1; }
            #pragma unroll
            for (int off = 16; off > 0; off >>= 1){
                float ov  = __shfl_xor_sync(FULL, v, off);
                int   oid = __shfl_xor_sync(FULL, idx, off);
                if (ov > v || (ov == v && oid < idx)) { v = ov; idx = oid; }
            }
            float sc = Sc[tl * 66 + idx];
            if (i < TOPK) ssum += sc;
            if (lane == i) { myval = sc; myidx = idx; mybv = v; }
            if (idx == e0) b0v = -INFINITY;
            if (idx == e1) b1v = -INFINITY;
        }

        // gap check among ranks 1..9 (lanes 0..7 vs next)
        float nxt = __shfl_down_sync(FULL, mybv, 1);
        bool close = (lane < 8) && (mybv - nxt < TAU);
        bool risky = __any_sync(FULL, close);

        if (!risky){
            const float scale = ROUTE_SCALE / (ssum + 1e-20f);
            if (lane < TOPK && gt < T){
                out[(size_t)gt * TOPK + lane]                    = myval * scale;
                out[(size_t)T * TOPK + (size_t)gt * TOPK + lane] = (float)myidx;
            }
        } else {
            // exact fp64 recompute of the 10 candidate logits, then re-rank
            const float* xr = x + (size_t)gt * H;
            double sc_d = 0.0, bd = -1e300;
            #pragma unroll 1
            for (int j = 0; j < 10; j++){
                int e = __shfl_sync(FULL, myidx, j);
                const float* wr = w + (size_t)e * H;
                double s = 0.0;
                #pragma unroll 4
                for (int m = 0; m < 16; m++){
                    int k = (m * 32 + lane) * 4;
                    float4 xv = *(const float4*)(xr + k);
                    float4 wv = *(const float4*)(wr + k);
                    s += (double)xv.x * wv.x + (double)xv.y * wv.y
                       + (double)xv.z * wv.z + (double)xv.w * wv.w;
                }
                #pragma unroll
                for (int off = 16; off > 0; off >>= 1)
                    s += __shfl_xor_sync(FULL, s, off);
                if (lane == j){
                    double sig = 1.0 / (1.0 + exp(-s));
                    sc_d = sig;
                    bd   = sig + (double)Sb[myidx];
                }
            }
            double rb = (lane < 10) ? bd : -1e300;
            int    ri = (lane < 10) ? myidx : (1 << 30);
            int rank = 0;
            #pragma unroll 1
            for (int l = 0; l < 10; l++){
                double ob = __shfl_sync(FULL, rb, l);
                int    oi = __shfl_sync(FULL, ri, l);
                if (ob > rb || (ob == rb && oi < ri)) rank++;
            }
            double contrib = (lane < 10 && rank < TOPK) ? sc_d : 0.0;
            #pragma unroll
            for (int off = 16; off > 0; off >>= 1)
                contrib += __shfl_xor_sync(FULL, contrib, off);
            const float scale = ROUTE_SCALE / ((float)contrib + 1e-20f);
            if (lane < 10 && rank < TOPK && gt < T){
                out[(size_t)gt * TOPK + rank]                    = (float)sc_d * scale;
                out[(size_t)T * TOPK + (size_t)gt * TOPK + rank] = (float)myidx;
            }
        }
    }
}

extern "C" void kernel_launch(void* const* d_in, const int* in_sizes, int n_in,
                              void* d_out, int out_size)
{
    const float* x    = (const float*)d_in[0];
    const float* bias = (const float*)d_in[1];
    const float* w    = (const float*)d_in[2];

    const int E = in_sizes[1];                   // 64
    const int H = in_sizes[2] / E;               // 2048
    const int T = in_sizes[0] / H;               // 16384

    cudaFuncSetAttribute(router_main, cudaFuncAttributeMaxDynamicSharedMemorySize, DYN_BYTES);

    prep_w_kernel<<<(E * (H / 2) + 255) / 256, 256>>>(w, H);
    router_main<<<T / TOKS, TPB, DYN_BYTES>>>(x, bias, w, (float*)d_out, T, H);
}

// round 14
// speedup vs baseline: 1.3462x; 1.3462x over previous
#include <cuda_runtime.h>
#include <cuda_bf16.h>
#include <math.h>
#include <stdint.h>

// AfmoeTokenChoiceRouter — 3x-bf16-split mma.sync GEMM (6 products) + fp64 boundary refinement
// logits = x[T,H] @ W^T (T=16384, H=2048, E=64); sigmoid; biased top-8; norm; *2.5
// Output: [ top_scores (T*8 f32) | selected_experts as f32 (T*8) ]
// R14: fix R13's B-copy bug (192/768 uint4 copied, wrong chunk stride). TPB=512,
//      warp tile 32x16, 6 of 9 level-products, R10-identical selection epilogue.

#define TOKS   128
#define TPB    512
#define TOPK   8
#define ROUTE_SCALE 2.5f
#define TAU    5e-5f

#define A_RS    40                   // A row stride in words (32 data + 8 pad)
#define A_LVL   (TOKS * A_RS)        // 5120 words per level
#define B_LVL   1024                 // 2 ks * 64 n * 8 words
#define B_CHUNK_U4 768               // per-chunk B image: 3*B_LVL words / 4
#define BUFW    (3*A_LVL + 3*B_LVL)  // 18432 words
#define B_OFF   (3*A_LVL)
#define DYN_BYTES (2 * BUFW * 4)     // 147456

// Pre-split W image: [kb(64)][lvl(3)][ks(2)][n(64)][pos(8)] bf16x2 words
__device__ uint32_t g_B[196608];

static __device__ __forceinline__ uint32_t pk2(__nv_bfloat16 a, __nv_bfloat16 b){
    return ((uint32_t)__bfloat16_as_ushort(b) << 16) | (uint32_t)__bfloat16_as_ushort(a);
}
static __device__ __forceinline__ void mma_bf16(float* c,
        uint32_t a0, uint32_t a1, uint32_t a2, uint32_t a3,
        uint32_t b0, uint32_t b1){
    asm volatile("mma.sync.aligned.m16n8k16.row.col.f32.bf16.bf16.f32 "
        "{%0,%1,%2,%3}, {%4,%5,%6,%7}, {%8,%9}, {%0,%1,%2,%3};"
        : "+f"(c[0]), "+f"(c[1]), "+f"(c[2]), "+f"(c[3])
        : "r"(a0), "r"(a1), "r"(a2), "r"(a3), "r"(b0), "r"(b1));
}

// ---------- prep: exact 3-level bf16 split of W, frag-permuted ----------
__global__ void prep_w_kernel(const float* __restrict__ w, int H){
    int half = H >> 1;
    int idx = blockIdx.x * blockDim.x + threadIdx.x;
    if (idx >= 64 * half) return;
    int e  = idx / half;
    int k  = (idx - e * half) * 2;
    float v0 = w[(size_t)e * H + k];
    float v1 = w[(size_t)e * H + k + 1];
    int kb = k >> 5, ks = (k >> 4) & 1, j = (k & 15) >> 1;
    int pos = (j < 4) ? 2 * j : 2 * (j - 4) + 1;
    size_t base = (size_t)kb * 3072 + (size_t)ks * 512 + (size_t)e * 8 + pos;
    #pragma unroll
    for (int L = 0; L < 3; L++){
        __nv_bfloat16 h0 = __float2bfloat16(v0);
        __nv_bfloat16 h1 = __float2bfloat16(v1);
        g_B[base + (size_t)L * 1024] = pk2(h0, h1);
        v0 -= __bfloat162float(h0);
        v1 -= __bfloat162float(h1);
    }
}

// ---------- main ----------
__global__ __launch_bounds__(TPB, 1)
void router_main(const float* __restrict__ x, const float* __restrict__ bias,
                 const float* __restrict__ w, float* __restrict__ out, int T, int H)
{
    extern __shared__ __align__(16) uint32_t dyn[];
    __shared__ float Sb[64];

    const int tid  = threadIdx.x;
    const int warp = tid >> 5;
    const int lane = tid & 31;
    const int wm   = warp & 3;          // 32 tokens
    const int wn   = warp >> 2;         // 16 experts
    const int g    = lane >> 2;
    const int c    = lane & 3;
    const int tok0 = blockIdx.x * TOKS;
    const int nchunk = H >> 5;

    if (tid < 64) Sb[tid] = bias[tid];

    // staging: 1 row per thread (4 threads per row cover k 0..31)
    const int rrow = tid >> 2;          // 0..127
    const int sks  = (tid >> 1) & 1;
    const int sh   = tid & 1;
    const float* xp = x + (size_t)(tok0 + rrow) * H + sks * 16 + sh * 4;

    float4 va[2];
    uint4  vb0, vb1;
    const uint4* gB4 = (const uint4*)g_B;

    va[0] = *(const float4*)(xp);
    va[1] = *(const float4*)(xp + 8);
    vb0 = gB4[tid & 511];                         // uint4 idx 0..511 (all threads)
    if (tid < B_CHUNK_U4 - 512) vb1 = gB4[512 + tid];   // idx 512..767

    float acc[2][2][4];
    #pragma unroll
    for (int mb = 0; mb < 2; mb++)
        #pragma unroll
        for (int nb = 0; nb < 2; nb++)
            #pragma unroll
            for (int q = 0; q < 4; q++) acc[mb][nb][q] = 0.0f;

    for (int kb = 0; kb < nchunk; kb++){
        uint32_t* Ab = dyn + (kb & 1) * BUFW;
        uint32_t* Bb = Ab + B_OFF;

        // ---- A: exact 3-level split, frag-permuted, 3x STS.128 ----
        {
            float e0 = va[0].x, e1 = va[0].y, e2 = va[0].z, e3 = va[0].w;
            float e4 = va[1].x, e5 = va[1].y, e6 = va[1].z, e7 = va[1].w;
            const int addr = rrow * A_RS + sks * 16 + sh * 4;
            #pragma unroll
            for (int L = 0; L < 3; L++){
                __nv_bfloat16 h0 = __float2bfloat16(e0), h1 = __float2bfloat16(e1);
                __nv_bfloat16 h2 = __float2bfloat16(e2), h3 = __float2bfloat16(e3);
                __nv_bfloat16 h4 = __float2bfloat16(e4), h5 = __float2bfloat16(e5);
                __nv_bfloat16 h6 = __float2bfloat16(e6), h7 = __float2bfloat16(e7);
                uint4 s;
                s.x = pk2(h0, h1); s.y = pk2(h4, h5);
                s.z = pk2(h2, h3); s.w = pk2(h6, h7);
                *(uint4*)(Ab + L * A_LVL + addr) = s;
                if (L < 2){
                    e0 -= __bfloat162float(h0); e1 -= __bfloat162float(h1);
                    e2 -= __bfloat162float(h2); e3 -= __bfloat162float(h3);
                    e4 -= __bfloat162float(h4); e5 -= __bfloat162float(h5);
                    e6 -= __bfloat162float(h6); e7 -= __bfloat162float(h7);
                }
            }
        }
        // ---- B: full 768-uint4 chunk image (FIX: was 192 in R13) ----
        *(uint4*)(Bb + tid * 4) = vb0;
        if (tid < B_CHUNK_U4 - 512) *(uint4*)(Bb + (512 + tid) * 4) = vb1;
        __syncthreads();

        // ---- prefetch next chunk (correct stride: 768 uint4 per chunk) ----
        if (kb + 1 < nchunk){
            const float* p = xp + (size_t)(kb + 1) * 32;
            va[0] = *(const float4*)(p);
            va[1] = *(const float4*)(p + 8);
            const size_t cb = (size_t)(kb + 1) * B_CHUNK_U4;
            vb0 = gB4[cb + tid];
            if (tid < B_CHUNK_U4 - 512) vb1 = gB4[cb + 512 + tid];
        }

        // ---- mma: 6 level-products {hh,hm,mh,hl,lh,mm} ----
        #pragma unroll
        for (int ks = 0; ks < 2; ks++){
            uint2 bf[3][2];
            #pragma unroll
            for (int L = 0; L < 3; L++)
                #pragma unroll
                for (int nb = 0; nb < 2; nb++)
                    bf[L][nb] = *(const uint2*)(Bb + L * B_LVL + ks * 512
                                                + (wn * 16 + nb * 8 + g) * 8 + 2 * c);
            uint2 A1[2][2], A2[2][2], A3[2][2];   // [mb][row-half]
            #pragma unroll
            for (int mb = 0; mb < 2; mb++){
                const int ab = (wm * 32 + mb * 16 + g) * A_RS + ks * 16 + 2 * c;
                A1[mb][0] = *(const uint2*)(Ab + ab);
                A1[mb][1] = *(const uint2*)(Ab + ab + 8 * A_RS);
                A2[mb][0] = *(const uint2*)(Ab + A_LVL + ab);
                A2[mb][1] = *(const uint2*)(Ab + A_LVL + ab + 8 * A_RS);
                A3[mb][0] = *(const uint2*)(Ab + 2 * A_LVL + ab);
                A3[mb][1] = *(const uint2*)(Ab + 2 * A_LVL + ab + 8 * A_RS);
            }
            // product-outer, acc-inner: 4 independent chains interleaved
            #pragma unroll
            for (int mb = 0; mb < 2; mb++)
                #pragma unroll
                for (int nb = 0; nb < 2; nb++)
                    mma_bf16(acc[mb][nb], A1[mb][0].x, A1[mb][1].x, A1[mb][0].y, A1[mb][1].y,
                             bf[0][nb].x, bf[0][nb].y);                       // h*h
            #pragma unroll
            for (int mb = 0; mb < 2; mb++)
                #pragma unroll
                for (int nb = 0; nb < 2; nb++)
                    mma_bf16(acc[mb][nb], A1[mb][0].x, A1[mb][1].x, A1[mb][0].y, A1[mb][1].y,
                             bf[1][nb].x, bf[1][nb].y);                       // h*m
            #pragma unroll
            for (int mb = 0; mb < 2; mb++)
                #pragma unroll
                for (int nb = 0; nb < 2; nb++)
                    mma_bf16(acc[mb][nb], A2[mb][0].x, A2[mb][1].x, A2[mb][0].y, A2[mb][1].y,
                             bf[0][nb].x, bf[0][nb].y);                       // m*h
            #pragma unroll
            for (int mb = 0; mb < 2; mb++)
                #pragma unroll
                for (int nb = 0; nb < 2; nb++)
                    mma_bf16(acc[mb][nb], A1[mb][0].x, A1[mb][1].x, A1[mb][0].y, A1[mb][1].y,
                             bf[2][nb].x, bf[2][nb].y);                       // h*l
            #pragma unroll
            for (int mb = 0; mb < 2; mb++)
                #pragma unroll
                for (int nb = 0; nb < 2; nb++)
                    mma_bf16(acc[mb][nb], A3[mb][0].x, A3[mb][1].x, A3[mb][0].y, A3[mb][1].y,
                             bf[0][nb].x, bf[0][nb].y);                       // l*h
            #pragma unroll
            for (int mb = 0; mb < 2; mb++)
                #pragma unroll
                for (int nb = 0; nb < 2; nb++)
                    mma_bf16(acc[mb][nb], A2[mb][0].x, A2[mb][1].x, A2[mb][0].y, A2[mb][1].y,
                             bf[1][nb].x, bf[1][nb].y);                       // m*m
        }
        __syncthreads();
    }

    // ---- epilogue: sigmoid -> SMEM score tile (stride 66) ----
    float* Sc = (float*)dyn;
    {
        const int r0 = wm * 32 + g;
        const int c0 = wn * 16 + 2 * c;
        #pragma unroll
        for (int mb = 0; mb < 2; mb++)
            #pragma unroll
            for (int nb = 0; nb < 2; nb++){
                int r  = r0 + mb * 16;
                int cc = c0 + nb * 8;
                Sc[r * 66 + cc]           = 1.0f / (1.0f + expf(-acc[mb][nb][0]));
                Sc[r * 66 + cc + 1]       = 1.0f / (1.0f + expf(-acc[mb][nb][1]));
                Sc[(r + 8) * 66 + cc]     = 1.0f / (1.0f + expf(-acc[mb][nb][2]));
                Sc[(r + 8) * 66 + cc + 1] = 1.0f / (1.0f + expf(-acc[mb][nb][3]));
            }
    }
    __syncthreads();

    // ---- top-10 selection + exact refinement (identical to passing R10) ----
    const unsigned FULL = 0xFFFFFFFFu;
    for (int t = 0; t < 8; t++){
        const int tl = warp * 8 + t;
        const int gt = tok0 + tl;
        const int e0 = lane, e1 = lane + 32;
        float b0v = Sc[tl * 66 + e0] + Sb[e0];
        float b1v = Sc[tl * 66 + e1] + Sb[e1];

        float myval = 0.0f, mybv = -1e30f;
        int   myidx = 0;
        float ssum  = 0.0f;

        #pragma unroll
        for (int i = 0; i < 10; i++){
            float v; int idx;
            if (b0v >= b1v) { v = b0v; idx = e0; }
            else            { v = b1v; idx = e1; }
            #pragma unroll
            for (int off = 16; off > 0; off >>= 1){
                float ov  = __shfl_xor_sync(FULL, v, off);
                int   oid = __shfl_xor_sync(FULL, idx, off);
                if (ov > v || (ov == v && oid < idx)) { v = ov; idx = oid; }
            }
            float sc = Sc[tl * 66 + idx];
            if (i < TOPK) ssum += sc;
            if (lane == i) { myval = sc; myidx = idx; mybv = v; }
            if (idx == e0) b0v = -INFINITY;
            if (idx == e1) b1v = -INFINITY;
        }

        float nxt = __shfl_down_sync(FULL, mybv, 1);
        bool close = (lane < 8) && (mybv - nxt < TAU);
        bool risky = __any_sync(FULL, close);

        if (!risky){
            const float scale = ROUTE_SCALE / (ssum + 1e-20f);
            if (lane < TOPK && gt < T){
                out[(size_t)gt * TOPK + lane]                    = myval * scale;
                out[(size_t)T * TOPK + (size_t)gt * TOPK + lane] = (float)myidx;
            }
        } else {
            const float* xr = x + (size_t)gt * H;
            double sc_d = 0.0, bd = -1e300;
            #pragma unroll 1
            for (int j = 0; j < 10; j++){
                int e = __shfl_sync(FULL, myidx, j);
                const float* wr = w + (size_t)e * H;
                double s = 0.0;
                #pragma unroll 4
                for (int m = 0; m < 16; m++){
                    int k = (m * 32 + lane) * 4;
                    float4 xv = *(const float4*)(xr + k);
                    float4 wv = *(const float4*)(wr + k);
                    s += (double)xv.x * wv.x + (double)xv.y * wv.y
                       + (double)xv.z * wv.z + (double)xv.w * wv.w;
                }
                #pragma unroll
                for (int off = 16; off > 0; off >>= 1)
                    s += __shfl_xor_sync(FULL, s, off);
                if (lane == j){
                    double sig = 1.0 / (1.0 + exp(-s));
                    sc_d = sig;
                    bd   = sig + (double)Sb[myidx];
                }
            }
            double rb = (lane < 10) ? bd : -1e300;
            int    ri = (lane < 10) ? myidx : (1 << 30);
            int rank = 0;
            #pragma unroll 1
            for (int l = 0; l < 10; l++){
                double ob = __shfl_sync(FULL, rb, l);
                int    oi = __shfl_sync(FULL, ri, l);
                if (ob > rb || (ob == rb && oi < ri)) rank++;
            }
            double contrib = (lane < 10 && rank < TOPK) ? sc_d : 0.0;
            #pragma unroll
            for (int off = 16; off > 0; off >>= 1)
                contrib += __shfl_xor_sync(FULL, contrib, off);
            const float scale = ROUTE_SCALE / ((float)contrib + 1e-20f);
            if (lane < 10 && rank < TOPK && gt < T){
                out[(size_t)gt * TOPK + rank]                    = (float)sc_d * scale;
                out[(size_t)T * TOPK + (size_t)gt * TOPK + rank] = (float)myidx;
            }
        }
    }
}

extern "C" void kernel_launch(void* const* d_in, const int* in_sizes, int n_in,
                              void* d_out, int out_size)
{
    const float* x    = (const float*)d_in[0];
    const float* bias = (const float*)d_in[1];
    const float* w    = (const float*)d_in[2];

    const int E = in_sizes[1];                   // 64
    const int H = in_sizes[2] / E;               // 2048
    const int T = in_sizes[0] / H;               // 16384

    cudaFuncSetAttribute(router_main, cudaFuncAttributeMaxDynamicSharedMemorySize, DYN_BYTES);

    prep_w_kernel<<<(E * (H / 2) + 255) / 256, 256>>>(w, H);
    router_main<<<T / TOKS, TPB, DYN_BYTES>>>(x, bias, w, (float*)d_out, T, H);
}

// round 16
// speedup vs baseline: 1.3681x; 1.0162x over previous
#include <cuda_runtime.h>
#include <cuda_bf16.h>
#include <math.h>
#include <stdint.h>

// AfmoeTokenChoiceRouter — barrier-free 3x-bf16-split mma.sync GEMM + fp64 refinement
// logits = x[T,H] @ W^T (T=16384, H=2048, E=64); sigmoid; biased top-8; norm; *2.5
// Output: [ top_scores (T*8 f32) | selected_experts as f32 (T*8) ]
// R16: fix R15's B-load units bug (uint2 index used word-scale constants).
//      Otherwise identical: no mainloop barriers, per-warp 32x16 tile stream,
//      in-register exact truncation split, 8 acc chains, R10/R14-proven epilogue.

#define TOKS   128
#define TPB    512
#define TOPK   8
#define ROUTE_SCALE 2.5f
#define TAU    5e-5f

#define DYN_BYTES (128 * 66 * 4)     // score tile only

// Pre-split W image: [kb(64)][lvl(3)][ks(2)][n(64)][pos(8)] bf16x2 words
__device__ uint32_t g_B[196608];

static __device__ __forceinline__ uint32_t pk2(__nv_bfloat16 a, __nv_bfloat16 b){
    return ((uint32_t)__bfloat16_as_ushort(b) << 16) | (uint32_t)__bfloat16_as_ushort(a);
}
static __device__ __forceinline__ void mma_bf16(float* c,
        uint32_t a0, uint32_t a1, uint32_t a2, uint32_t a3,
        uint32_t b0, uint32_t b1){
    asm volatile("mma.sync.aligned.m16n8k16.row.col.f32.bf16.bf16.f32 "
        "{%0,%1,%2,%3}, {%4,%5,%6,%7}, {%8,%9}, {%0,%1,%2,%3};"
        : "+f"(c[0]), "+f"(c[1]), "+f"(c[2]), "+f"(c[3])
        : "r"(a0), "r"(a1), "r"(a2), "r"(a3), "r"(b0), "r"(b1));
}

// Exact truncation split of a float2 into 3 bf16x2 frag words (v == h+m+l).
static __device__ __forceinline__ void split3(float2 f,
        uint32_t& s1, uint32_t& s2, uint32_t& s3){
    uint32_t u0 = __float_as_uint(f.x), u1 = __float_as_uint(f.y);
    s1 = __byte_perm(u0, u1, 0x7632);
    float r0 = f.x - __uint_as_float(u0 & 0xFFFF0000u);
    float r1 = f.y - __uint_as_float(u1 & 0xFFFF0000u);
    uint32_t v0 = __float_as_uint(r0), v1 = __float_as_uint(r1);
    s2 = __byte_perm(v0, v1, 0x7632);
    float q0 = r0 - __uint_as_float(v0 & 0xFFFF0000u);
    float q1 = r1 - __uint_as_float(v1 & 0xFFFF0000u);
    s3 = __byte_perm(__float_as_uint(q0), __float_as_uint(q1), 0x7632);
}

// ---------- prep: exact 3-level bf16 split of W, frag-permuted (unchanged) ----------
__global__ void prep_w_kernel(const float* __restrict__ w, int H){
    int half = H >> 1;
    int idx = blockIdx.x * blockDim.x + threadIdx.x;
    if (idx >= 64 * half) return;
    int e  = idx / half;
    int k  = (idx - e * half) * 2;
    float v0 = w[(size_t)e * H + k];
    float v1 = w[(size_t)e * H + k + 1];
    int kb = k >> 5, ks = (k >> 4) & 1, j = (k & 15) >> 1;
    int pos = (j < 4) ? 2 * j : 2 * (j - 4) + 1;
    size_t base = (size_t)kb * 3072 + (size_t)ks * 512 + (size_t)e * 8 + pos;
    #pragma unroll
    for (int L = 0; L < 3; L++){
        __nv_bfloat16 h0 = __float2bfloat16(v0);
        __nv_bfloat16 h1 = __float2bfloat16(v1);
        g_B[base + (size_t)L * 1024] = pk2(h0, h1);
        v0 -= __bfloat162float(h0);
        v1 -= __bfloat162float(h1);
    }
}

// ---------- main ----------
__global__ __launch_bounds__(TPB, 1)
void router_main(const float* __restrict__ x, const float* __restrict__ bias,
                 const float* __restrict__ w, float* __restrict__ out, int T, int H)
{
    extern __shared__ __align__(16) float Sc[];   // [128][66] score tile
    __shared__ float Sb[64];

    const int tid  = threadIdx.x;
    const int warp = tid >> 5;
    const int lane = tid & 31;
    const int wm   = warp & 3;          // 32 tokens
    const int wn   = warp >> 2;         // 16 experts
    const int g    = lane >> 2;
    const int c    = lane & 3;
    const int tok0 = blockIdx.x * TOKS;
    const int nchunk = H >> 5;

    if (tid < 64) Sb[tid] = bias[tid];

    // Per-warp stream: rows base + {0,8,16,24} + g
    const float* Arow[4];
    #pragma unroll
    for (int r = 0; r < 4; r++)
        Arow[r] = x + (size_t)(tok0 + wm * 32 + r * 8 + g) * H;

    float accP[2][2][4], accQ[2][2][4];
    #pragma unroll
    for (int mb = 0; mb < 2; mb++)
        #pragma unroll
        for (int nb = 0; nb < 2; nb++)
            #pragma unroll
            for (int q = 0; q < 4; q++){ accP[mb][nb][q] = 0.0f; accQ[mb][nb][q] = 0.0f; }

    const int nbase = wn * 16 + g;      // B column base (nb adds 8)

    for (int kb = 0; kb < nchunk; kb++){
        // ---- A loads: 16x LDG.64, issued back-to-back (MLP) ----
        float2 fA[4][2][2];             // [row][ks][h]
        #pragma unroll
        for (int r = 0; r < 4; r++){
            const float2* Ap = (const float2*)(Arow[r] + kb * 32) + c;
            #pragma unroll
            for (int ks = 0; ks < 2; ks++)
                #pragma unroll
                for (int h = 0; h < 2; h++)
                    fA[r][ks][h] = Ap[ks * 8 + h * 4];
        }
        // ---- B loads: 12x LDG.64 from L2-resident image ----
        // uint2 units: level = 512, ks = 256, n = 4  (FIX: R15 had these halved)
        uint2 fB[2][3][2];              // [ks][L][nb]
        {
            const uint2* Bp = (const uint2*)(g_B + (size_t)kb * 3072);
            #pragma unroll
            for (int ks = 0; ks < 2; ks++)
                #pragma unroll
                for (int L = 0; L < 3; L++)
                    #pragma unroll
                    for (int nb = 0; nb < 2; nb++)
                        fB[ks][L][nb] = Bp[L * 512 + ks * 256 + (nbase + nb * 8) * 4 + c];
        }
        // ---- convert A to 3-level frags (exact truncation split) ----
        uint32_t Af[2][3][2][4];        // [ks][L][mb][a0..a3]
        #pragma unroll
        for (int ks = 0; ks < 2; ks++)
            #pragma unroll
            for (int mb = 0; mb < 2; mb++){
                split3(fA[2*mb    ][ks][0], Af[ks][0][mb][0], Af[ks][1][mb][0], Af[ks][2][mb][0]);
                split3(fA[2*mb + 1][ks][0], Af[ks][0][mb][1], Af[ks][1][mb][1], Af[ks][2][mb][1]);
                split3(fA[2*mb    ][ks][1], Af[ks][0][mb][2], Af[ks][1][mb][2], Af[ks][2][mb][2]);
                split3(fA[2*mb + 1][ks][1], Af[ks][0][mb][3], Af[ks][1][mb][3], Af[ks][2][mb][3]);
            }
        // ---- mma: 6 products {hh,mh,lh}->P, {hm,mm,hl}->Q : 8 independent chains ----
        #pragma unroll
        for (int ks = 0; ks < 2; ks++){
            #pragma unroll
            for (int mb = 0; mb < 2; mb++)
                #pragma unroll
                for (int nb = 0; nb < 2; nb++)
                    mma_bf16(accP[mb][nb], Af[ks][0][mb][0], Af[ks][0][mb][1],
                             Af[ks][0][mb][2], Af[ks][0][mb][3],
                             fB[ks][0][nb].x, fB[ks][0][nb].y);               // h*h
            #pragma unroll
            for (int mb = 0; mb < 2; mb++)
                #pragma unroll
                for (int nb = 0; nb < 2; nb++)
                    mma_bf16(accQ[mb][nb], Af[ks][0][mb][0], Af[ks][0][mb][1],
                             Af[ks][0][mb][2], Af[ks][0][mb][3],
                             fB[ks][1][nb].x, fB[ks][1][nb].y);               // h*m
            #pragma unroll
            for (int mb = 0; mb < 2; mb++)
                #pragma unroll
                for (int nb = 0; nb < 2; nb++)
                    mma_bf16(accP[mb][nb], Af[ks][1][mb][0], Af[ks][1][mb][1],
                             Af[ks][1][mb][2], Af[ks][1][mb][3],
                             fB[ks][0][nb].x, fB[ks][0][nb].y);               // m*h
            #pragma unroll
            for (int mb = 0; mb < 2; mb++)
                #pragma unroll
                for (int nb = 0; nb < 2; nb++)
                    mma_bf16(accQ[mb][nb], Af[ks][0][mb][0], Af[ks][0][mb][1],
                             Af[ks][0][mb][2], Af[ks][0][mb][3],
                             fB[ks][2][nb].x, fB[ks][2][nb].y);               // h*l
            #pragma unroll
            for (int mb = 0; mb < 2; mb++)
                #pragma unroll
                for (int nb = 0; nb < 2; nb++)
                    mma_bf16(accP[mb][nb], Af[ks][2][mb][0], Af[ks][2][mb][1],
                             Af[ks][2][mb][2], Af[ks][2][mb][3],
                             fB[ks][0][nb].x, fB[ks][0][nb].y);               // l*h
            #pragma unroll
            for (int mb = 0; mb < 2; mb++)
                #pragma unroll
                for (int nb = 0; nb < 2; nb++)
                    mma_bf16(accQ[mb][nb], Af[ks][1][mb][0], Af[ks][1][mb][1],
                             Af[ks][1][mb][2], Af[ks][1][mb][3],
                             fB[ks][1][nb].x, fB[ks][1][nb].y);               // m*m
        }
    }

    // ---- epilogue: merge chains, sigmoid -> SMEM score tile (stride 66) ----
    {
        const int r0 = wm * 32 + g;
        const int c0 = wn * 16 + 2 * c;
        #pragma unroll
        for (int mb = 0; mb < 2; mb++)
            #pragma unroll
            for (int nb = 0; nb < 2; nb++){
                int r  = r0 + mb * 16;
                int cc = c0 + nb * 8;
                float v0 = accP[mb][nb][0] + accQ[mb][nb][0];
                float v1 = accP[mb][nb][1] + accQ[mb][nb][1];
                float v2 = accP[mb][nb][2] + accQ[mb][nb][2];
                float v3 = accP[mb][nb][3] + accQ[mb][nb][3];
                Sc[r * 66 + cc]           = 1.0f / (1.0f + expf(-v0));
                Sc[r * 66 + cc + 1]       = 1.0f / (1.0f + expf(-v1));
                Sc[(r + 8) * 66 + cc]     = 1.0f / (1.0f + expf(-v2));
                Sc[(r + 8) * 66 + cc + 1] = 1.0f / (1.0f + expf(-v3));
            }
    }
    __syncthreads();

    // ---- top-10 selection + exact refinement (identical to passing R10/R14) ----
    const unsigned FULL = 0xFFFFFFFFu;
    for (int t = 0; t < 8; t++){
        const int tl = warp * 8 + t;
        const int gt = tok0 + tl;
        const int e0 = lane, e1 = lane + 32;
        float b0v = Sc[tl * 66 + e0] + Sb[e0];
        float b1v = Sc[tl * 66 + e1] + Sb[e1];

        float myval = 0.0f, mybv = -1e30f;
        int   myidx = 0;
        float ssum  = 0.0f;

        #pragma unroll
        for (int i = 0; i < 10; i++){
            float v; int idx;
            if (b0v >= b1v) { v = b0v; idx = e0; }
            else            { v = b1v; idx = e1; }
            #pragma unroll
            for (int off = 16; off > 0; off >>= 1){
                float ov  = __shfl_xor_sync(FULL, v, off);
                int   oid = __shfl_xor_sync(FULL, idx, off);
                if (ov > v || (ov == v && oid < idx)) { v = ov; idx = oid; }
            }
            float sc = Sc[tl * 66 + idx];
            if (i < TOPK) ssum += sc;
            if (lane == i) { myval = sc; myidx = idx; mybv = v; }
            if (idx == e0) b0v = -INFINITY;
            if (idx == e1) b1v = -INFINITY;
        }

        float nxt = __shfl_down_sync(FULL, mybv, 1);
        bool close = (lane < 8) && (mybv - nxt < TAU);
        bool risky = __any_sync(FULL, close);

        if (!risky){
            const float scale = ROUTE_SCALE / (ssum + 1e-20f);
            if (lane < TOPK && gt < T){
                out[(size_t)gt * TOPK + lane]                    = myval * scale;
                out[(size_t)T * TOPK + (size_t)gt * TOPK + lane] = (float)myidx;
            }
        } else {
            const float* xr = x + (size_t)gt * H;
            double sc_d = 0.0, bd = -1e300;
            #pragma unroll 1
            for (int j = 0; j < 10; j++){
                int e = __shfl_sync(FULL, myidx, j);
                const float* wr = w + (size_t)e * H;
                double s = 0.0;
                #pragma unroll 4
                for (int m = 0; m < 16; m++){
                    int k = (m * 32 + lane) * 4;
                    float4 xv = *(const float4*)(xr + k);
                    float4 wv = *(const float4*)(wr + k);
                    s += (double)xv.x * wv.x + (double)xv.y * wv.y
                       + (double)xv.z * wv.z + (double)xv.w * wv.w;
                }
                #pragma unroll
                for (int off = 16; off > 0; off >>= 1)
                    s += __shfl_xor_sync(FULL, s, off);
                if (lane == j){
                    double sig = 1.0 / (1.0 + exp(-s));
                    sc_d = sig;
                    bd   = sig + (double)Sb[myidx];
                }
            }
            double rb = (lane < 10) ? bd : -1e300;
            int    ri = (lane < 10) ? myidx : (1 << 30);
            int rank = 0;
            #pragma unroll 1
            for (int l = 0; l < 10; l++){
                double ob = __shfl_sync(FULL, rb, l);
                int    oi = __shfl_sync(FULL, ri, l);
                if (ob > rb || (ob == rb && oi < ri)) rank++;
            }
            double contrib = (lane < 10 && rank < TOPK) ? sc_d : 0.0;
            #pragma unroll
            for (int off = 16; off > 0; off >>= 1)
                contrib += __shfl_xor_sync(FULL, contrib, off);
            const float scale = ROUTE_SCALE / ((float)contrib + 1e-20f);
            if (lane < 10 && rank < TOPK && gt < T){
                out[(size_t)gt * TOPK + rank]                    = (float)sc_d * scale;
                out[(size_t)T * TOPK + (size_t)gt * TOPK + rank] = (float)myidx;
            }
        }
    }
}

extern "C" void kernel_launch(void* const* d_in, const int* in_sizes, int n_in,
                              void* d_out, int out_size)
{
    const float* x    = (const float*)d_in[0];
    const float* bias = (const float*)d_in[1];
    const float* w    = (const float*)d_in[2];

    const int E = in_sizes[1];                   // 64
    const int H = in_sizes[2] / E;               // 2048
    const int T = in_sizes[0] / H;               // 16384

    prep_w_kernel<<<(E * (H / 2) + 255) / 256, 256>>>(w, H);
    router_main<<<T / TOKS, TPB, DYN_BYTES>>>(x, bias, w, (float*)d_out, T, H);
}